// round 3
// baseline (speedup 1.0000x reference)
#include <cuda_runtime.h>
#include <math.h>

#define KGT 50
#define NA 3
#define NC 80
#define GX 32               // blocks per (scale,batch); MUST be 32 (== warp size)
#define BMAX 16
#define NGRP (3*BMAX)
#define NPART (NGRP*GX)

__device__ double g_pmain[NPART];
__device__ double g_phigh[NPART];
__device__ int    g_php[NPART];
__device__ int    g_count;       // zero-init; reset by finalize block each run

__device__ __forceinline__ float sigf(float x){ return 1.0f/(1.0f+expf(-x)); }

__device__ __forceinline__ float iou_f(float ax,float ay,float aw,float ah,
                                       float bx,float by,float bw,float bh){
    float tlx=fmaxf(ax-aw*0.5f, bx-bw*0.5f);
    float tly=fmaxf(ay-ah*0.5f, by-bh*0.5f);
    float brx=fminf(ax+aw*0.5f, bx+bw*0.5f);
    float bry=fminf(ay+ah*0.5f, by+bh*0.5f);
    float wx=fmaxf(brx-tlx,0.0f), wy=fmaxf(bry-tly,0.0f);
    float inter=wx*wy;
    return inter/(aw*ah + bw*bh - inter);
}

__global__ void __launch_bounds__(256) k_fused(
        const float* __restrict__ o0, const float* __restrict__ o1,
        const float* __restrict__ o2, const float* __restrict__ tgt,
        const float* __restrict__ anc,
        int W0, int W1, int W2, int B, float* __restrict__ outp){
    int s = blockIdx.z, b = blockIdx.y, bx = blockIdx.x;
    const float* out  = (s==0) ? o0 : (s==1 ? o1 : o2);
    int W             = (s==0) ? W0 : (s==1 ? W1 : W2);
    const float* Aptr = anc + ((s==0) ? 12 : (s==1 ? 6 : 0));
    int HW = W*W, cells = NA*HW;
    int pidx = (s*B + b)*GX + bx;
    int tid  = threadIdx.x;
    int lane = tid & 31, wid = tid >> 5;

    __shared__ float s_l[KGT], s_t[KGT], s_r[KGT], s_btm[KGT], s_ar[KGT];
    __shared__ float s_d[KGT][4];
    __shared__ int   s_v[KGT], s_f[KGT], s_idx[KGT], s_cls[KGT];
    __shared__ int   s_rec[256];
    __shared__ double s_wm[8], s_wh[8];
    __shared__ int   s_last;

    // ---- phase 1+2: per-GT box, validity, cell, best anchor, delta ----
    int my_valid = 0;
    if (tid < KGT){
        const float* t = tgt + (size_t)(b*KGT + tid)*5;
        float t0=t[0], t1=t[1], t2=t[2], t3=t[3], t4=t[4];
        my_valid = ((t0+t1+t2+t3+t4) > 0.0f) ? 1 : 0;
        float gx=t0*(float)W, gy=t1*(float)W, gw=t2*(float)W, gh=t3*(float)W;
        s_v[tid]=my_valid;
        s_l[tid]=gx-gw*0.5f;  s_r[tid]  =gx+gw*0.5f;
        s_t[tid]=gy-gh*0.5f;  s_btm[tid]=gy+gh*0.5f;
        s_ar[tid]=gw*gh;
        s_cls[tid]=(int)t4;
        int cx = min(max((int)floorf(gx),0), W-1);
        int cy = min(max((int)floorf(gy),0), W-1);
        int astar = 0; float best = -1e30f;
        #pragma unroll
        for (int a=0; a<NA; a++){
            float v = iou_f((float)cx+0.5f, (float)cy+0.5f, Aptr[a*2], Aptr[a*2+1],
                            gx, gy, gw, gh);
            if (v > best){ best = v; astar = a; }   // strict >: first max (argmax)
        }
        s_f[tid]   = (cy*W + cx)*NA + astar;        // dedup key
        s_idx[tid] = astar*HW + (cy*W + cx);        // cell index in thread layout
        s_d[tid][0] = gx - (float)cx;
        s_d[tid][1] = gy - (float)cy;
        s_d[tid][2] = gw / Aptr[astar*2+0];
        s_d[tid][3] = gh / Aptr[astar*2+1];
    }
    s_rec[tid] = -1;
    int numobj = __syncthreads_count(my_valid);     // barrier + count of valid GTs

    // ---- phase 3: last-valid-wins dedup + direct scatter into this block's range ----
    if (tid < KGT && my_valid){
        int f = s_f[tid], win = 1;
        for (int k2 = tid+1; k2 < KGT; k2++)
            if (s_v[k2] && s_f[k2]==f){ win = 0; break; }
        if (win){
            int rel = s_idx[tid] - bx*256;
            if (rel >= 0 && rel < 256) s_rec[rel] = tid;
        }
    }
    __syncthreads();

    // ---- phase 4: per-cell loss ----
    int idx = bx*256 + tid;
    double vm = 0.0, vh = 0.0;
    float m = -1.0f;
    bool active = (idx < cells);
    if (active){
        int a = idx / HW, hw = idx - a*HW;
        int x = hw % W,   y  = hw / W;
        const float* base = out + (size_t)(b*255 + a*85)*HW + hw;
        float c0 = base[0];
        float c1 = base[(size_t)HW];
        float c2 = base[(size_t)2*HW];
        float c3 = base[(size_t)3*HW];
        float c4 = base[(size_t)4*HW];
        float sx = sigf(c0), sy = sigf(c1);
        float ew = expf(c2), eh = expf(c3);
        float conf = sigf(c4);
        float a0 = Aptr[a*2], a1 = Aptr[a*2+1];
        float px = sx + (float)x, py = sy + (float)y;
        float pw = ew*a0, ph = eh*a1;
        float pl = px-pw*0.5f, pr = px+pw*0.5f;
        float pt = py-ph*0.5f, pb = py+ph*0.5f;
        float pa = pw*ph;
        #pragma unroll 5
        for (int k=0;k<KGT;k++){
            if (s_v[k]){
                float wx = fminf(pr, s_r[k])   - fmaxf(pl, s_l[k]);
                float wy = fminf(pb, s_btm[k]) - fmaxf(pt, s_t[k]);
                wx = fmaxf(wx, 0.0f); wy = fmaxf(wy, 0.0f);
                float inter = wx*wy;
                m = fmaxf(m, inter / (pa + s_ar[k] - inter));
            }
        }
        int rec = s_rec[tid];
        if (rec >= 0){
            float di = 5.0f*(conf - m);               // obj_iou at winner == m
            float dx = sx - s_d[rec][0];
            float dy = sy - s_d[rec][1];
            float dw = ew - s_d[rec][2];
            float dh = eh - s_d[rec][3];
            float mx = -1e30f;
            for (int c=0;c<NC;c++) mx = fmaxf(mx, base[(size_t)(5+c)*HW]);
            float sm = 0.0f;
            for (int c=0;c<NC;c++) sm += expf(base[(size_t)(5+c)*HW] - mx);
            float lse = mx + logf(sm);
            float tl  = base[(size_t)(5+s_cls[rec])*HW];
            vm = 0.5*(double)(di*di)
               + 0.5*(double)(dx*dx + dy*dy + dw*dw + dh*dh)
               + (double)(lse - tl);
        } else if (numobj > 0){
            double c2s = 0.5*(double)(conf*conf);
            vm = c2s;
            if (m >= 0.7f) vh = c2s;                  // subtracted iff has_pos
        }
    }
    int hpAll = __syncthreads_or(active && (m > 0.7f));

    // ---- block reduction (warp shuffles, deterministic) ----
    #pragma unroll
    for (int off=16; off>0; off>>=1){
        vm += __shfl_down_sync(0xffffffffu, vm, off);
        vh += __shfl_down_sync(0xffffffffu, vh, off);
    }
    if (lane == 0){ s_wm[wid]=vm; s_wh[wid]=vh; }
    __syncthreads();
    if (tid == 0){
        double bm=0.0, bh=0.0;
        #pragma unroll
        for (int w=0; w<8; w++){ bm+=s_wm[w]; bh+=s_wh[w]; }
        g_pmain[pidx]=bm; g_phigh[pidx]=bh; g_php[pidx]=hpAll;
        __threadfence();
        int total = gridDim.x*gridDim.y*gridDim.z;
        int old = atomicAdd(&g_count, 1);
        s_last = (old == total-1) ? 1 : 0;
    }
    __syncthreads();

    // ---- finalize by the last block to finish ----
    if (s_last){
        __threadfence();
        int ngroups = 3*B;
        int ntot = ngroups*GX;
        // grand main sum: parallel strided loads
        double tm = 0.0;
        for (int i = tid; i < ntot; i += 256) tm += g_pmain[i];
        #pragma unroll
        for (int off=16; off>0; off>>=1) tm += __shfl_down_sync(0xffffffffu, tm, off);
        if (lane == 0) s_wm[wid] = tm;
        // per-group high adjustment: warp w handles groups w, w+8, ...
        double adj = 0.0;
        for (int g = wid; g < ngroups; g += 8){
            double h  = g_phigh[g*GX + lane];
            int    hp = g_php  [g*GX + lane];
            int hpAny = __any_sync(0xffffffffu, hp != 0);
            #pragma unroll
            for (int off=16; off>0; off>>=1) h += __shfl_down_sync(0xffffffffu, h, off);
            if (lane == 0 && hpAny) adj += h;
        }
        if (lane == 0) s_wh[wid] = adj;
        __syncthreads();
        if (tid == 0){
            double main_s = 0.0, adj_s = 0.0;
            #pragma unroll
            for (int w=0; w<8; w++){ main_s += s_wm[w]; adj_s += s_wh[w]; }
            outp[0] = (float)((main_s - adj_s) / ((double)B * 3.0));
            g_count = 0;                         // reset for next graph replay
        }
    }
}

extern "C" void kernel_launch(void* const* d_in, const int* in_sizes, int n_in,
                              void* d_out, int out_size){
    const float* o0  = (const float*)d_in[0];
    const float* o1  = (const float*)d_in[1];
    const float* o2  = (const float*)d_in[2];
    const float* tgt = (const float*)d_in[3];
    const float* anc = (const float*)d_in[4];
    int B = in_sizes[3] / (KGT*5);
    int Ws[3];
    for (int i=0;i<3;i++){
        int hw = in_sizes[i] / (B*255);
        int w = 1; while (w*w < hw) w++;
        Ws[i] = w;
    }
    dim3 grid(GX, B, 3);
    k_fused<<<grid, 256>>>(o0, o1, o2, tgt, anc, Ws[0], Ws[1], Ws[2], B, (float*)d_out);
}

// round 4
// speedup vs baseline: 1.1447x; 1.1447x over previous
#include <cuda_runtime.h>
#include <math.h>

#define KGT 50
#define NA 3
#define NC 80
#define GX 32               // blocks per (scale,batch); MUST be 32 (== warp size)
#define BMAX 16
#define NGRP (3*BMAX)
#define NPART (NGRP*GX)

__device__ double g_pmain[NPART];
__device__ double g_phigh[NPART];
__device__ int    g_php[NPART];
__device__ int    g_count;       // zero-init; reset by finalize block each run

__device__ __forceinline__ float sigf(float x){ return 1.0f/(1.0f+expf(-x)); }

__device__ __forceinline__ float iou_f(float ax,float ay,float aw,float ah,
                                       float bx,float by,float bw,float bh){
    float tlx=fmaxf(ax-aw*0.5f, bx-bw*0.5f);
    float tly=fmaxf(ay-ah*0.5f, by-bh*0.5f);
    float brx=fminf(ax+aw*0.5f, bx+bw*0.5f);
    float bry=fminf(ay+ah*0.5f, by+bh*0.5f);
    float wx=fmaxf(brx-tlx,0.0f), wy=fmaxf(bry-tly,0.0f);
    float inter=wx*wy;
    return inter/(aw*ah + bw*bh - inter);
}

__global__ void __launch_bounds__(256) k_fused(
        const float* __restrict__ o0, const float* __restrict__ o1,
        const float* __restrict__ o2, const float* __restrict__ tgt,
        const float* __restrict__ anc,
        int W0, int W1, int W2, int B, float* __restrict__ outp){
    int s = blockIdx.z, b = blockIdx.y, bx = blockIdx.x;
    const float* out  = (s==0) ? o0 : (s==1 ? o1 : o2);
    int W             = (s==0) ? W0 : (s==1 ? W1 : W2);
    const float* Aptr = anc + ((s==0) ? 12 : (s==1 ? 6 : 0));
    int HW = W*W, cells = NA*HW;
    int pidx = (s*B + b)*GX + bx;
    int tid  = threadIdx.x;
    int lane = tid & 31, wid = tid >> 5;

    __shared__ float4 s_box[KGT];          // (l, t, r, b) ; invalid -> degenerate
    __shared__ float  s_ar07[KGT];         // 0.7 * area   ; invalid -> 0.7
    __shared__ float  s_ar[KGT];           // area         ; invalid -> 1.0
    __shared__ float  s_d[KGT][4];
    __shared__ int    s_v[KGT], s_f[KGT], s_idx[KGT], s_cls[KGT];
    __shared__ int    s_rec[256];
    __shared__ double s_wm[8], s_wh[8];
    __shared__ int    s_last;

    // ---- phase 1+2: per-GT box, validity, cell, best anchor, delta ----
    int my_valid = 0;
    if (tid < KGT){
        const float* t = tgt + (size_t)(b*KGT + tid)*5;
        float t0=t[0], t1=t[1], t2=t[2], t3=t[3], t4=t[4];
        my_valid = ((t0+t1+t2+t3+t4) > 0.0f) ? 1 : 0;
        float gx=t0*(float)W, gy=t1*(float)W, gw=t2*(float)W, gh=t3*(float)W;
        s_v[tid]=my_valid;
        if (my_valid){
            s_box[tid] = make_float4(gx-gw*0.5f, gy-gh*0.5f, gx+gw*0.5f, gy+gh*0.5f);
            s_ar[tid]  = gw*gh;
            s_ar07[tid]= 0.7f*gw*gh;
        } else {
            // degenerate: intersection always clamps to 0, lhs = -0.7 never fires,
            // exact-pass iou = 0/(pa+1) = 0 (matches ref max when >=1 valid GT)
            s_box[tid] = make_float4(2e30f, 2e30f, -2e30f, -2e30f);
            s_ar[tid]  = 1.0f;
            s_ar07[tid]= 0.7f;
        }
        s_cls[tid]=(int)t4;
        int cx = min(max((int)floorf(gx),0), W-1);
        int cy = min(max((int)floorf(gy),0), W-1);
        int astar = 0; float best = -1e30f;
        #pragma unroll
        for (int a=0; a<NA; a++){
            float v = iou_f((float)cx+0.5f, (float)cy+0.5f, Aptr[a*2], Aptr[a*2+1],
                            gx, gy, gw, gh);
            if (v > best){ best = v; astar = a; }   // strict >: first max (argmax)
        }
        s_f[tid]   = (cy*W + cx)*NA + astar;        // dedup key
        s_idx[tid] = astar*HW + (cy*W + cx);        // cell index in thread layout
        s_d[tid][0] = gx - (float)cx;
        s_d[tid][1] = gy - (float)cy;
        s_d[tid][2] = gw / Aptr[astar*2+0];
        s_d[tid][3] = gh / Aptr[astar*2+1];
    }
    s_rec[tid] = -1;
    int numobj = __syncthreads_count(my_valid);

    // ---- phase 3: last-valid-wins dedup + scatter into this block's range ----
    if (tid < KGT && my_valid){
        int f = s_f[tid], win = 1;
        for (int k2 = tid+1; k2 < KGT; k2++)
            if (s_v[k2] && s_f[k2]==f){ win = 0; break; }
        if (win){
            int rel = s_idx[tid] - bx*256;
            if (rel >= 0 && rel < 256) s_rec[rel] = tid;
        }
    }
    __syncthreads();

    // ---- phase 4: per-cell loss ----
    int idx = bx*256 + tid;
    double vm = 0.0, vh = 0.0;
    bool gtp = false;
    bool active = (idx < cells);
    if (active){
        int a = idx / HW, hw = idx - a*HW;
        int x = hw % W,   y  = hw / W;
        const float* base = out + (size_t)(b*255 + a*85)*HW + hw;
        float c0 = base[0];
        float c1 = base[(size_t)HW];
        float c2 = base[(size_t)2*HW];
        float c3 = base[(size_t)3*HW];
        float c4 = base[(size_t)4*HW];
        float sx = sigf(c0), sy = sigf(c1);
        float ew = expf(c2), eh = expf(c3);
        float conf = sigf(c4);
        float a0 = Aptr[a*2], a1 = Aptr[a*2+1];
        float px = sx + (float)x, py = sy + (float)y;
        float pw = ew*a0, ph = eh*a1;
        float pl = px-pw*0.5f, pr = px+pw*0.5f;
        float pt = py-ph*0.5f, pb = py+ph*0.5f;
        float pa = pw*ph;
        float pa07 = 0.7f*pa;

        // hot loop: NO division, NO branch. iou_k >= 0.7  <=>  lhs_k >= 0.7*pa
        float maxlhs = -1e30f;
        #pragma unroll 5
        for (int k=0;k<KGT;k++){
            float4 bb = s_box[k];
            float wx = fminf(pr, bb.z) - fmaxf(pl, bb.x);
            float wy = fminf(pb, bb.w) - fmaxf(pt, bb.y);
            wx = fmaxf(wx, 0.0f); wy = fmaxf(wy, 0.0f);
            float inter = wx*wy;
            maxlhs = fmaxf(maxlhs, fmaf(inter, 1.7f, -s_ar07[k]));
        }
        bool ge = (maxlhs >= pa07);
        gtp     = (maxlhs >  pa07);

        int rec = s_rec[tid];
        if (rec >= 0){
            // rare winner cell: exact max-IoU with true division
            float m = -1.0f;
            for (int k=0;k<KGT;k++){
                float4 bb = s_box[k];
                float wx = fminf(pr, bb.z) - fmaxf(pl, bb.x);
                float wy = fminf(pb, bb.w) - fmaxf(pt, bb.y);
                wx = fmaxf(wx, 0.0f); wy = fmaxf(wy, 0.0f);
                float inter = wx*wy;
                m = fmaxf(m, inter / (pa + s_ar[k] - inter));
            }
            float di = 5.0f*(conf - m);               // obj_iou at winner == m
            float dx = sx - s_d[rec][0];
            float dy = sy - s_d[rec][1];
            float dw = ew - s_d[rec][2];
            float dh = eh - s_d[rec][3];
            float mx = -1e30f;
            for (int c=0;c<NC;c++) mx = fmaxf(mx, base[(size_t)(5+c)*HW]);
            float sm = 0.0f;
            for (int c=0;c<NC;c++) sm += expf(base[(size_t)(5+c)*HW] - mx);
            float lse = mx + logf(sm);
            float tl  = base[(size_t)(5+s_cls[rec])*HW];
            vm = 0.5*(double)(di*di)
               + 0.5*(double)(dx*dx + dy*dy + dw*dw + dh*dh)
               + (double)(lse - tl);
        } else if (numobj > 0){
            double c2s = 0.5*(double)(conf*conf);
            vm = c2s;
            if (ge) vh = c2s;                         // subtracted iff has_pos
        }
    }
    int hpAll = __syncthreads_or(active && gtp);

    // ---- block reduction (warp shuffles, deterministic) ----
    #pragma unroll
    for (int off=16; off>0; off>>=1){
        vm += __shfl_down_sync(0xffffffffu, vm, off);
        vh += __shfl_down_sync(0xffffffffu, vh, off);
    }
    if (lane == 0){ s_wm[wid]=vm; s_wh[wid]=vh; }
    __syncthreads();
    if (tid == 0){
        double bm=0.0, bh=0.0;
        #pragma unroll
        for (int w=0; w<8; w++){ bm+=s_wm[w]; bh+=s_wh[w]; }
        g_pmain[pidx]=bm; g_phigh[pidx]=bh; g_php[pidx]=hpAll;
        __threadfence();
        int total = gridDim.x*gridDim.y*gridDim.z;
        int old = atomicAdd(&g_count, 1);
        s_last = (old == total-1) ? 1 : 0;
    }
    __syncthreads();

    // ---- finalize by the last block to finish ----
    if (s_last){
        __threadfence();
        int ngroups = 3*B;
        int ntot = ngroups*GX;
        double tm = 0.0;
        for (int i = tid; i < ntot; i += 256) tm += g_pmain[i];
        #pragma unroll
        for (int off=16; off>0; off>>=1) tm += __shfl_down_sync(0xffffffffu, tm, off);
        if (lane == 0) s_wm[wid] = tm;
        double adj = 0.0;
        for (int g = wid; g < ngroups; g += 8){
            double h  = g_phigh[g*GX + lane];
            int    hp = g_php  [g*GX + lane];
            int hpAny = __any_sync(0xffffffffu, hp != 0);
            #pragma unroll
            for (int off=16; off>0; off>>=1) h += __shfl_down_sync(0xffffffffu, h, off);
            if (lane == 0 && hpAny) adj += h;
        }
        if (lane == 0) s_wh[wid] = adj;
        __syncthreads();
        if (tid == 0){
            double main_s = 0.0, adj_s = 0.0;
            #pragma unroll
            for (int w=0; w<8; w++){ main_s += s_wm[w]; adj_s += s_wh[w]; }
            outp[0] = (float)((main_s - adj_s) / ((double)B * 3.0));
            g_count = 0;                         // reset for next graph replay
        }
    }
}

extern "C" void kernel_launch(void* const* d_in, const int* in_sizes, int n_in,
                              void* d_out, int out_size){
    const float* o0  = (const float*)d_in[0];
    const float* o1  = (const float*)d_in[1];
    const float* o2  = (const float*)d_in[2];
    const float* tgt = (const float*)d_in[3];
    const float* anc = (const float*)d_in[4];
    int B = in_sizes[3] / (KGT*5);
    int Ws[3];
    for (int i=0;i<3;i++){
        int hw = in_sizes[i] / (B*255);
        int w = 1; while (w*w < hw) w++;
        Ws[i] = w;
    }
    dim3 grid(GX, B, 3);
    k_fused<<<grid, 256>>>(o0, o1, o2, tgt, anc, Ws[0], Ws[1], Ws[2], B, (float*)d_out);
}